// round 13
// baseline (speedup 1.0000x reference)
#include <cuda_runtime.h>
#include <cuda_bf16.h>
#include <cuda_fp16.h>
#include <cstdint>

#define NN    50000
#define EE    800000
#define NPAD  50048
#define NTILES (NPAD / 128)          // 391 row-tiles of 128

// ---------------- scratch (device globals; no allocation allowed) -----------
__device__ __align__(16) __half g_Pv[(size_t)NPAD * 128];  // projected (gather), fp16
__device__ __align__(16) float  g_C [(size_t)NPAD * 128];  // self term, fp32
__device__ __align__(16) float  g_bias[3][128];            // bl + bs per layer
__device__ uint4 g_Ahi4[(size_t)NPAD * 16];                // A frags [r16][ks][lane]
__device__ uint4 g_Alo4[(size_t)NPAD * 16];
__device__ uint2 g_Bhi2[3][32 * 8 * 32];                   // B frags per layer
__device__ uint2 g_Blo2[3][32 * 8 * 32];
__device__ int g_deg[NPAD];
__device__ int g_rowoff[NPAD + 1];
__device__ int g_fill[NPAD];
__device__ int g_srcl[EE];

// ---------------- helpers ----------------------------------------------------
__device__ __forceinline__ void mma16816(float* c, const uint4& a, const uint2& b) {
    asm("mma.sync.aligned.m16n8k16.row.col.f32.bf16.bf16.f32 "
        "{%0,%1,%2,%3}, {%4,%5,%6,%7}, {%8,%9}, {%0,%1,%2,%3};"
        : "+f"(c[0]), "+f"(c[1]), "+f"(c[2]), "+f"(c[3])
        : "r"(a.x), "r"(a.y), "r"(a.z), "r"(a.w), "r"(b.x), "r"(b.y));
}

__device__ __forceinline__ void split2(float f0, float f1, uint32_t& hw, uint32_t& lw) {
    __nv_bfloat16 h0 = __float2bfloat16(f0);
    __nv_bfloat16 h1 = __float2bfloat16(f1);
    __nv_bfloat16 l0 = __float2bfloat16(f0 - __bfloat162float(h0));
    __nv_bfloat16 l1 = __float2bfloat16(f1 - __bfloat162float(h1));
    hw = (uint32_t)__bfloat16_as_ushort(h0) | ((uint32_t)__bfloat16_as_ushort(h1) << 16);
    lw = (uint32_t)__bfloat16_as_ushort(l0) | ((uint32_t)__bfloat16_as_ushort(l1) << 16);
}

// ---------------- CSR build --------------------------------------------------
__global__ void k_zero_deg() {
    int i = blockIdx.x * blockDim.x + threadIdx.x;
    if (i < NPAD) g_deg[i] = 0;
}
__global__ void k_count(const int* __restrict__ dst) {
    int e = blockIdx.x * blockDim.x + threadIdx.x;
    if (e < EE) atomicAdd(&g_deg[dst[e]], 1);
}
__global__ void __launch_bounds__(1024) k_scan() {
    __shared__ int ssum[1024];
    int t = threadIdx.x;
    const int CH = (NN + 1023) / 1024;
    int b0 = t * CH;
    int e0 = min(b0 + CH, NN);
    int s = 0;
    for (int i = b0; i < e0; i++) s += g_deg[i];
    ssum[t] = s;
    __syncthreads();
    for (int d = 1; d < 1024; d <<= 1) {
        int v = (t >= d) ? ssum[t - d] : 0;
        __syncthreads();
        ssum[t] += v;
        __syncthreads();
    }
    int run = ssum[t] - s;
    for (int i = b0; i < e0; i++) {
        g_rowoff[i] = run;
        g_fill[i]   = run;
        run += g_deg[i];
    }
    if (t == 1023) g_rowoff[NN] = run;
}
__global__ void k_place(const int* __restrict__ src, const int* __restrict__ dst) {
    int e = blockIdx.x * blockDim.x + threadIdx.x;
    if (e < EE) {
        int p = atomicAdd(&g_fill[dst[e]], 1);
        g_srcl[p] = src[e];
    }
}

// ---------------- convA: fp32 x[N,128] -> fragment-layout bf16 hi/lo --------
__global__ void __launch_bounds__(256)
k_convA(const float* __restrict__ A) {
    int idx = blockIdx.x * blockDim.x + threadIdx.x;
    if (idx >= NPAD * 16) return;
    int r16  = idx >> 8;
    int ks   = (idx >> 5) & 7;
    int lane = idx & 31;
    int r = r16 * 16 + (lane >> 2);
    int c = ks * 16 + (lane & 3) * 2;

    float2 p00 = (r     < NN) ? *(const float2*)(A + (size_t)r * 128 + c)
                              : make_float2(0.f, 0.f);
    float2 p10 = (r + 8 < NN) ? *(const float2*)(A + (size_t)(r + 8) * 128 + c)
                              : make_float2(0.f, 0.f);
    float2 p01 = (r     < NN) ? *(const float2*)(A + (size_t)r * 128 + c + 8)
                              : make_float2(0.f, 0.f);
    float2 p11 = (r + 8 < NN) ? *(const float2*)(A + (size_t)(r + 8) * 128 + c + 8)
                              : make_float2(0.f, 0.f);

    uint4 hv, lv;
    split2(p00.x, p00.y, hv.x, lv.x);
    split2(p10.x, p10.y, hv.y, lv.y);
    split2(p01.x, p01.y, hv.z, lv.z);
    split2(p11.x, p11.y, hv.w, lv.w);
    g_Ahi4[idx] = hv;
    g_Alo4[idx] = lv;
}

// ---------------- convB: fused [Wl | Wr+Ws] -> per-layer fragments + bias ---
__global__ void __launch_bounds__(256)
k_convB(const float* __restrict__ Wl, const float* __restrict__ Wr,
        const float* __restrict__ Ws, const float* __restrict__ bl,
        const float* __restrict__ bs, int dout, int layer) {
    int dout2 = 2 * dout;
    int items = (dout2 / 8) * 256;
    int idx = blockIdx.x * blockDim.x + threadIdx.x;
    if (idx < items) {
        int ntile = idx >> 8;
        int ks    = (idx >> 5) & 7;
        int lane  = idx & 31;
        int n  = ntile * 8 + (lane >> 2);
        int k0 = ks * 16 + (lane & 3) * 2;

        float v[4];
#pragma unroll
        for (int i = 0; i < 4; i++) {
            int k = k0 + (i >> 1) * 8 + (i & 1);
            v[i] = (n < dout) ? Wl[k * dout + n]
                              : Wr[k * dout + (n - dout)] + Ws[k * dout + (n - dout)];
        }
        uint2 hv, lv;
        split2(v[0], v[1], hv.x, lv.x);
        split2(v[2], v[3], hv.y, lv.y);
        g_Bhi2[layer][idx] = hv;
        g_Blo2[layer][idx] = lv;
    }
    if (idx < dout) g_bias[layer][idx] = bl[idx] + bs[idx];
}

// ---------------- HMMA GEMM -> P (fp16) and C (fp32) ------------------------
__global__ void __launch_bounds__(256)
k_mm(int dout, int layer) {
    int tid = threadIdx.x, wid = tid >> 5, lane = tid & 31;
    int wr = wid & 3, wc = wid >> 2;
    int tileRow = blockIdx.x, colB = blockIdx.y;
    int r16b = tileRow * 8 + wr * 2;
    int ntb  = colB * 16 + wc * 8;
    const uint2* BH = g_Bhi2[layer];
    const uint2* BL = g_Blo2[layer];

    float acc[2][8][4];
#pragma unroll
    for (int m = 0; m < 2; m++)
#pragma unroll
        for (int j = 0; j < 8; j++)
#pragma unroll
            for (int q = 0; q < 4; q++) acc[m][j][q] = 0.f;

#pragma unroll
    for (int ks = 0; ks < 8; ks++) {
        uint4 ah0 = g_Ahi4[((size_t)(r16b + 0) * 8 + ks) * 32 + lane];
        uint4 ah1 = g_Ahi4[((size_t)(r16b + 1) * 8 + ks) * 32 + lane];
        uint4 al0 = g_Alo4[((size_t)(r16b + 0) * 8 + ks) * 32 + lane];
        uint4 al1 = g_Alo4[((size_t)(r16b + 1) * 8 + ks) * 32 + lane];
        uint2 bh[8], bl_[8];
#pragma unroll
        for (int j = 0; j < 8; j++) {
            bh[j]  = BH[((ntb + j) * 8 + ks) * 32 + lane];
            bl_[j] = BL[((ntb + j) * 8 + ks) * 32 + lane];
        }
#pragma unroll
        for (int j = 0; j < 8; j++) {
            mma16816(acc[0][j], ah0, bh[j]);
            mma16816(acc[1][j], ah1, bh[j]);
            mma16816(acc[0][j], ah0, bl_[j]);
            mma16816(acc[1][j], ah1, bl_[j]);
            mma16816(acc[0][j], al0, bh[j]);
            mma16816(acc[1][j], al1, bh[j]);
        }
    }

#pragma unroll
    for (int m = 0; m < 2; m++) {
        int r = tileRow * 128 + wr * 32 + m * 16 + (lane >> 2);
#pragma unroll
        for (int j = 0; j < 8; j++) {
            int col = colB * 128 + wc * 64 + j * 8 + (lane & 3) * 2;
            if (col < dout) {
                *(__half2*)(g_Pv + (size_t)r * dout + col) =
                    __floats2half2_rn(acc[m][j][0], acc[m][j][1]);
                *(__half2*)(g_Pv + (size_t)(r + 8) * dout + col) =
                    __floats2half2_rn(acc[m][j][2], acc[m][j][3]);
            } else {
                int cc = col - dout;
                *(float2*)(g_C + (size_t)r * dout + cc) =
                    make_float2(acc[m][j][0], acc[m][j][1]);
                *(float2*)(g_C + (size_t)(r + 8) * dout + cc) =
                    make_float2(acc[m][j][2], acc[m][j][3]);
            }
        }
    }
}

// ---------------- fused aggregate + epilogue + fragment write ---------------
template <int CPR8, int DOUT>
__global__ void __launch_bounds__(256)
k_agg(float* __restrict__ out, int writeOut, int relu, int layer) {
    int gid  = blockIdx.x * blockDim.x + threadIdx.x;
    int node = gid / CPR8;
    int cidx = gid % CPR8;
    if (node >= NN) return;
    int c0  = cidx * 8;
    int beg = g_rowoff[node];
    int end = g_rowoff[node + 1];

    const uint4* P4 = (const uint4*)g_Pv;
    float acc[8];
#pragma unroll
    for (int i = 0; i < 8; i++) acc[i] = 0.f;

    int j = beg;
    // MLP-8 unrolled gather
    for (; j + 8 <= end; j += 8) {
        int s[8];
#pragma unroll
        for (int u = 0; u < 8; u++) s[u] = __ldg(&g_srcl[j + u]);
        uint4 v[8];
#pragma unroll
        for (int u = 0; u < 8; u++) v[u] = P4[(size_t)s[u] * CPR8 + cidx];
#pragma unroll
        for (int u = 0; u < 8; u++) {
            uint32_t w[4] = {v[u].x, v[u].y, v[u].z, v[u].w};
#pragma unroll
            for (int q = 0; q < 4; q++) {
                float2 f = __half22float2(*(__half2*)&w[q]);
                acc[2 * q]     += f.x;
                acc[2 * q + 1] += f.y;
            }
        }
    }
    for (; j + 2 <= end; j += 2) {
        int s0 = __ldg(&g_srcl[j]);
        int s1 = __ldg(&g_srcl[j + 1]);
        uint4 v0 = P4[(size_t)s0 * CPR8 + cidx];
        uint4 v1 = P4[(size_t)s1 * CPR8 + cidx];
        uint32_t w0[4] = {v0.x, v0.y, v0.z, v0.w};
        uint32_t w1[4] = {v1.x, v1.y, v1.z, v1.w};
#pragma unroll
        for (int q = 0; q < 4; q++) {
            float2 f0 = __half22float2(*(__half2*)&w0[q]);
            float2 f1 = __half22float2(*(__half2*)&w1[q]);
            acc[2 * q]     += f0.x + f1.x;
            acc[2 * q + 1] += f0.y + f1.y;
        }
    }
    if (j < end) {
        int s = __ldg(&g_srcl[j]);
        uint4 v = P4[(size_t)s * CPR8 + cidx];
        uint32_t w[4] = {v.x, v.y, v.z, v.w};
#pragma unroll
        for (int q = 0; q < 4; q++) {
            float2 f = __half22float2(*(__half2*)&w[q]);
            acc[2 * q]     += f.x;
            acc[2 * q + 1] += f.y;
        }
    }
    float inv = 1.0f / fmaxf((float)(end - beg), 1.0f);

    float4 C0 = *(const float4*)(g_C + (size_t)node * DOUT + c0);
    float4 C1 = *(const float4*)(g_C + (size_t)node * DOUT + c0 + 4);
    float4 b0 = *(const float4*)(&g_bias[layer][c0]);
    float4 b1 = *(const float4*)(&g_bias[layer][c0 + 4]);
    float o[8];
    o[0] = acc[0] * inv + C0.x + b0.x;  o[1] = acc[1] * inv + C0.y + b0.y;
    o[2] = acc[2] * inv + C0.z + b0.z;  o[3] = acc[3] * inv + C0.w + b0.w;
    o[4] = acc[4] * inv + C1.x + b1.x;  o[5] = acc[5] * inv + C1.y + b1.y;
    o[6] = acc[6] * inv + C1.z + b1.z;  o[7] = acc[7] * inv + C1.w + b1.w;
    if (relu) {
#pragma unroll
        for (int i = 0; i < 8; i++) o[i] = fmaxf(o[i], 0.f);
    }

    if (writeOut) {
        *(float4*)(out + (size_t)node * DOUT + c0)     = make_float4(o[0], o[1], o[2], o[3]);
        *(float4*)(out + (size_t)node * DOUT + c0 + 4) = make_float4(o[4], o[5], o[6], o[7]);
    } else {
        // write bf16 hi/lo fragments for next layer's A (row=node, cols c0..c0+7)
        int r16  = node >> 4;
        int ks   = c0 >> 4;
        int word = (((c0 >> 3) & 1) << 1) | ((node >> 3) & 1);
        uint32_t* AH = (uint32_t*)g_Ahi4;
        uint32_t* AL = (uint32_t*)g_Alo4;
        size_t base = ((size_t)r16 * 256 + (size_t)ks * 32) * 4;
#pragma unroll
        for (int p = 0; p < 4; p++) {
            int lane = ((node & 7) << 2) | p;
            uint32_t hw, lw;
            split2(o[2 * p], o[2 * p + 1], hw, lw);
            AH[base + lane * 4 + word] = hw;
            AL[base + lane * 4 + word] = lw;
        }
    }
}

// ---------------- launch ----------------------------------------------------
static cudaStream_t g_s2;
static cudaEvent_t  g_evFork, g_evJoin, g_evB0;
static bool g_init = false;

extern "C" void kernel_launch(void* const* d_in, const int* in_sizes, int n_in,
                              void* d_out, int out_size) {
    if (!g_init) {
        cudaStreamCreateWithFlags(&g_s2, cudaStreamNonBlocking);
        cudaEventCreateWithFlags(&g_evFork, cudaEventDisableTiming);
        cudaEventCreateWithFlags(&g_evJoin, cudaEventDisableTiming);
        cudaEventCreateWithFlags(&g_evB0, cudaEventDisableTiming);
        g_init = true;
    }

    const float* x   = (const float*)d_in[0];
    const int*   ei  = (const int*)d_in[1];   // JAX x64 disabled -> int32
    const int*   src = ei;
    const int*   dst = ei + EE;

    const float* Wl[3] = {(const float*)d_in[4],  (const float*)d_in[9],  (const float*)d_in[14]};
    const float* bl[3] = {(const float*)d_in[5],  (const float*)d_in[10], (const float*)d_in[15]};
    const float* Wr[3] = {(const float*)d_in[6],  (const float*)d_in[11], (const float*)d_in[16]};
    const float* Ws[3] = {(const float*)d_in[7],  (const float*)d_in[12], (const float*)d_in[17]};
    const float* bs[3] = {(const float*)d_in[8],  (const float*)d_in[13], (const float*)d_in[18]};

    const int TB = 256;
    const int douts[3] = {128, 128, 64};

    // ---- fork: convB x3 then CSR build on side stream ----
    cudaEventRecord(g_evFork, 0);
    cudaStreamWaitEvent(g_s2, g_evFork, 0);
    for (int L = 0; L < 3; L++) {
        int bItems = (2 * douts[L] / 8) * 256;
        k_convB<<<(bItems + TB - 1) / TB, TB, 0, g_s2>>>(
            Wl[L], Wr[L], Ws[L], bl[L], bs[L], douts[L], L);
        if (L == 0) cudaEventRecord(g_evB0, g_s2);
    }
    k_zero_deg<<<(NPAD + TB - 1) / TB, TB, 0, g_s2>>>();
    k_count<<<(EE + TB - 1) / TB, TB, 0, g_s2>>>(dst);
    k_scan<<<1, 1024, 0, g_s2>>>();
    k_place<<<(EE + TB - 1) / TB, TB, 0, g_s2>>>(src, dst);
    cudaEventRecord(g_evJoin, g_s2);

    // ---- main chain: convA -> (mm -> agg) x3 ----
    k_convA<<<(NPAD * 16 + TB - 1) / TB, TB>>>(x);
    cudaStreamWaitEvent(0, g_evB0, 0);   // B0 ready before mm0

    for (int L = 0; L < 3; L++) {
        int dout  = douts[L];
        int dout2 = 2 * dout;
        int last  = (L == 2);

        dim3 gg(NTILES, dout2 / 128);
        k_mm<<<gg, 256>>>(dout, L);

        if (L == 0) cudaStreamWaitEvent(0, g_evJoin, 0);  // CSR + B1/B2 ready

        if (dout == 128) {
            k_agg<16, 128><<<(NN * 16 + TB - 1) / TB, TB>>>(
                (float*)d_out, last ? 1 : 0, last ? 0 : 1, L);
        } else {
            k_agg<8, 64><<<(NN * 8 + TB - 1) / TB, TB>>>(
                (float*)d_out, last ? 1 : 0, last ? 0 : 1, L);
        }
    }
}

// round 14
// speedup vs baseline: 1.0919x; 1.0919x over previous
#include <cuda_runtime.h>
#include <cuda_bf16.h>
#include <cuda_fp16.h>
#include <cstdint>

#define NN    50000
#define EE    800000
#define NPAD  50048
#define NTILES (NPAD / 128)          // 391 row-tiles of 128

// ---------------- scratch (device globals; no allocation allowed) -----------
__device__ __align__(16) __half g_Pv[(size_t)NPAD * 128];  // projected (gather), fp16
__device__ __align__(16) float  g_C [(size_t)NPAD * 128];  // self term, fp32
__device__ __align__(16) float  g_bias[3][128];            // bl + bs per layer
__device__ uint4 g_Ahi4[(size_t)NPAD * 16];                // A frags [r16][ks][lane]
__device__ uint4 g_Alo4[(size_t)NPAD * 16];
__device__ uint2 g_Bhi2[3][32 * 8 * 32];                   // B frags per layer
__device__ uint2 g_Blo2[3][32 * 8 * 32];
__device__ int g_deg[NPAD];
__device__ int g_rowoff[NPAD + 1];
__device__ int g_fill[NPAD];
__device__ int g_srcl[EE];

// ---------------- helpers ----------------------------------------------------
__device__ __forceinline__ void mma16816(float* c, const uint4& a, const uint2& b) {
    asm("mma.sync.aligned.m16n8k16.row.col.f32.bf16.bf16.f32 "
        "{%0,%1,%2,%3}, {%4,%5,%6,%7}, {%8,%9}, {%0,%1,%2,%3};"
        : "+f"(c[0]), "+f"(c[1]), "+f"(c[2]), "+f"(c[3])
        : "r"(a.x), "r"(a.y), "r"(a.z), "r"(a.w), "r"(b.x), "r"(b.y));
}

__device__ __forceinline__ void split2(float f0, float f1, uint32_t& hw, uint32_t& lw) {
    __nv_bfloat16 h0 = __float2bfloat16(f0);
    __nv_bfloat16 h1 = __float2bfloat16(f1);
    __nv_bfloat16 l0 = __float2bfloat16(f0 - __bfloat162float(h0));
    __nv_bfloat16 l1 = __float2bfloat16(f1 - __bfloat162float(h1));
    hw = (uint32_t)__bfloat16_as_ushort(h0) | ((uint32_t)__bfloat16_as_ushort(h1) << 16);
    lw = (uint32_t)__bfloat16_as_ushort(l0) | ((uint32_t)__bfloat16_as_ushort(l1) << 16);
}

// ---------------- CSR build --------------------------------------------------
__global__ void k_zero_deg() {
    int i = blockIdx.x * blockDim.x + threadIdx.x;
    if (i < NPAD) g_deg[i] = 0;
}
__global__ void k_count(const int* __restrict__ dst) {
    int e = blockIdx.x * blockDim.x + threadIdx.x;
    if (e < EE) atomicAdd(&g_deg[dst[e]], 1);
}
__global__ void __launch_bounds__(1024) k_scan() {
    __shared__ int ssum[1024];
    int t = threadIdx.x;
    const int CH = (NN + 1023) / 1024;
    int b0 = t * CH;
    int e0 = min(b0 + CH, NN);
    int s = 0;
    for (int i = b0; i < e0; i++) s += g_deg[i];
    ssum[t] = s;
    __syncthreads();
    for (int d = 1; d < 1024; d <<= 1) {
        int v = (t >= d) ? ssum[t - d] : 0;
        __syncthreads();
        ssum[t] += v;
        __syncthreads();
    }
    int run = ssum[t] - s;
    for (int i = b0; i < e0; i++) {
        g_rowoff[i] = run;
        g_fill[i]   = run;
        run += g_deg[i];
    }
    if (t == 1023) g_rowoff[NN] = run;
}
__global__ void k_place(const int* __restrict__ src, const int* __restrict__ dst) {
    int e = blockIdx.x * blockDim.x + threadIdx.x;
    if (e < EE) {
        int p = atomicAdd(&g_fill[dst[e]], 1);
        g_srcl[p] = src[e];
    }
}

// ---------------- convA: fp32 x[N,128] -> fragment-layout bf16 hi/lo --------
__global__ void __launch_bounds__(256)
k_convA(const float* __restrict__ A) {
    int idx = blockIdx.x * blockDim.x + threadIdx.x;
    if (idx >= NPAD * 16) return;
    int r16  = idx >> 8;
    int ks   = (idx >> 5) & 7;
    int lane = idx & 31;
    int r = r16 * 16 + (lane >> 2);
    int c = ks * 16 + (lane & 3) * 2;

    float2 p00 = (r     < NN) ? *(const float2*)(A + (size_t)r * 128 + c)
                              : make_float2(0.f, 0.f);
    float2 p10 = (r + 8 < NN) ? *(const float2*)(A + (size_t)(r + 8) * 128 + c)
                              : make_float2(0.f, 0.f);
    float2 p01 = (r     < NN) ? *(const float2*)(A + (size_t)r * 128 + c + 8)
                              : make_float2(0.f, 0.f);
    float2 p11 = (r + 8 < NN) ? *(const float2*)(A + (size_t)(r + 8) * 128 + c + 8)
                              : make_float2(0.f, 0.f);

    uint4 hv, lv;
    split2(p00.x, p00.y, hv.x, lv.x);
    split2(p10.x, p10.y, hv.y, lv.y);
    split2(p01.x, p01.y, hv.z, lv.z);
    split2(p11.x, p11.y, hv.w, lv.w);
    g_Ahi4[idx] = hv;
    g_Alo4[idx] = lv;
}

// ---------------- convB: fused [Wl | Wr+Ws] -> per-layer fragments + bias ---
__global__ void __launch_bounds__(256)
k_convB(const float* __restrict__ Wl, const float* __restrict__ Wr,
        const float* __restrict__ Ws, const float* __restrict__ bl,
        const float* __restrict__ bs, int dout, int layer) {
    int dout2 = 2 * dout;
    int items = (dout2 / 8) * 256;
    int idx = blockIdx.x * blockDim.x + threadIdx.x;
    if (idx < items) {
        int ntile = idx >> 8;
        int ks    = (idx >> 5) & 7;
        int lane  = idx & 31;
        int n  = ntile * 8 + (lane >> 2);
        int k0 = ks * 16 + (lane & 3) * 2;

        float v[4];
#pragma unroll
        for (int i = 0; i < 4; i++) {
            int k = k0 + (i >> 1) * 8 + (i & 1);
            v[i] = (n < dout) ? Wl[k * dout + n]
                              : Wr[k * dout + (n - dout)] + Ws[k * dout + (n - dout)];
        }
        uint2 hv, lv;
        split2(v[0], v[1], hv.x, lv.x);
        split2(v[2], v[3], hv.y, lv.y);
        g_Bhi2[layer][idx] = hv;
        g_Blo2[layer][idx] = lv;
    }
    if (idx < dout) g_bias[layer][idx] = bl[idx] + bs[idx];
}

// ---------------- HMMA GEMM -> P (fp16) and C (fp32) ------------------------
__global__ void __launch_bounds__(256)
k_mm(int dout, int layer) {
    int tid = threadIdx.x, wid = tid >> 5, lane = tid & 31;
    int wr = wid & 3, wc = wid >> 2;
    int tileRow = blockIdx.x, colB = blockIdx.y;
    int r16b = tileRow * 8 + wr * 2;
    int ntb  = colB * 16 + wc * 8;
    const uint2* BH = g_Bhi2[layer];
    const uint2* BL = g_Blo2[layer];

    float acc[2][8][4];
#pragma unroll
    for (int m = 0; m < 2; m++)
#pragma unroll
        for (int j = 0; j < 8; j++)
#pragma unroll
            for (int q = 0; q < 4; q++) acc[m][j][q] = 0.f;

#pragma unroll
    for (int ks = 0; ks < 8; ks++) {
        uint4 ah0 = g_Ahi4[((size_t)(r16b + 0) * 8 + ks) * 32 + lane];
        uint4 ah1 = g_Ahi4[((size_t)(r16b + 1) * 8 + ks) * 32 + lane];
        uint4 al0 = g_Alo4[((size_t)(r16b + 0) * 8 + ks) * 32 + lane];
        uint4 al1 = g_Alo4[((size_t)(r16b + 1) * 8 + ks) * 32 + lane];
        uint2 bh[8], bl_[8];
#pragma unroll
        for (int j = 0; j < 8; j++) {
            bh[j]  = BH[((ntb + j) * 8 + ks) * 32 + lane];
            bl_[j] = BL[((ntb + j) * 8 + ks) * 32 + lane];
        }
#pragma unroll
        for (int j = 0; j < 8; j++) {
            mma16816(acc[0][j], ah0, bh[j]);
            mma16816(acc[1][j], ah1, bh[j]);
            mma16816(acc[0][j], ah0, bl_[j]);
            mma16816(acc[1][j], ah1, bl_[j]);
            mma16816(acc[0][j], al0, bh[j]);
            mma16816(acc[1][j], al1, bh[j]);
        }
    }

#pragma unroll
    for (int m = 0; m < 2; m++) {
        int r = tileRow * 128 + wr * 32 + m * 16 + (lane >> 2);
#pragma unroll
        for (int j = 0; j < 8; j++) {
            int col = colB * 128 + wc * 64 + j * 8 + (lane & 3) * 2;
            if (col < dout) {
                *(__half2*)(g_Pv + (size_t)r * dout + col) =
                    __floats2half2_rn(acc[m][j][0], acc[m][j][1]);
                *(__half2*)(g_Pv + (size_t)(r + 8) * dout + col) =
                    __floats2half2_rn(acc[m][j][2], acc[m][j][3]);
            } else {
                int cc = col - dout;
                *(float2*)(g_C + (size_t)r * dout + cc) =
                    make_float2(acc[m][j][0], acc[m][j][1]);
                *(float2*)(g_C + (size_t)(r + 8) * dout + cc) =
                    make_float2(acc[m][j][2], acc[m][j][3]);
            }
        }
    }
}

// ---------------- fused aggregate: cooperative group gather -----------------
// CPR8 lanes per node (16 for DOUT=128, 8 for DOUT=64), lane handles 8 cols.
// Group loads CPR8 edge indices at once, shuffle-broadcasts, gathers in
// batches of 8 (MLP=8, index traffic cut CPR8x).
template <int CPR8, int DOUT>
__global__ void __launch_bounds__(256)
k_agg(float* __restrict__ out, int writeOut, int relu, int layer) {
    int gid  = blockIdx.x * blockDim.x + threadIdx.x;
    int node = gid / CPR8;
    int cidx = gid % CPR8;
    if (node >= NN) return;
    int c0  = cidx * 8;
    int beg = g_rowoff[node];
    int end = g_rowoff[node + 1];

    int lane = threadIdx.x & 31;
    int gb   = lane & ~(CPR8 - 1);
    unsigned gmask = ((1u << CPR8) - 1u) << gb;

    const uint4* P4 = (const uint4*)g_Pv;
    float acc[8];
#pragma unroll
    for (int i = 0; i < 8; i++) acc[i] = 0.f;

    int j = beg;
    for (; j + CPR8 <= end; j += CPR8) {
        int s_l = __ldg(&g_srcl[j + cidx]);
#pragma unroll
        for (int b = 0; b < CPR8; b += 8) {
            uint4 v[8];
#pragma unroll
            for (int u = 0; u < 8; u++) {
                int su = __shfl_sync(gmask, s_l, b + u, CPR8);
                v[u] = P4[(size_t)su * CPR8 + cidx];
            }
#pragma unroll
            for (int u = 0; u < 8; u++) {
                uint32_t w[4] = {v[u].x, v[u].y, v[u].z, v[u].w};
#pragma unroll
                for (int q = 0; q < 4; q++) {
                    float2 f = __half22float2(*(__half2*)&w[q]);
                    acc[2 * q]     += f.x;
                    acc[2 * q + 1] += f.y;
                }
            }
        }
    }
    int rem = end - j;
    if (rem > 0) {
        int s_l = (cidx < rem) ? __ldg(&g_srcl[j + cidx]) : 0;
        for (int u = 0; u < rem; u++) {
            int su = __shfl_sync(gmask, s_l, u, CPR8);
            uint4 v = P4[(size_t)su * CPR8 + cidx];
            uint32_t w[4] = {v.x, v.y, v.z, v.w};
#pragma unroll
            for (int q = 0; q < 4; q++) {
                float2 f = __half22float2(*(__half2*)&w[q]);
                acc[2 * q]     += f.x;
                acc[2 * q + 1] += f.y;
            }
        }
    }
    float inv = 1.0f / fmaxf((float)(end - beg), 1.0f);

    float4 C0 = *(const float4*)(g_C + (size_t)node * DOUT + c0);
    float4 C1 = *(const float4*)(g_C + (size_t)node * DOUT + c0 + 4);
    float4 b0 = *(const float4*)(&g_bias[layer][c0]);
    float4 b1 = *(const float4*)(&g_bias[layer][c0 + 4]);
    float o[8];
    o[0] = acc[0] * inv + C0.x + b0.x;  o[1] = acc[1] * inv + C0.y + b0.y;
    o[2] = acc[2] * inv + C0.z + b0.z;  o[3] = acc[3] * inv + C0.w + b0.w;
    o[4] = acc[4] * inv + C1.x + b1.x;  o[5] = acc[5] * inv + C1.y + b1.y;
    o[6] = acc[6] * inv + C1.z + b1.z;  o[7] = acc[7] * inv + C1.w + b1.w;
    if (relu) {
#pragma unroll
        for (int i = 0; i < 8; i++) o[i] = fmaxf(o[i], 0.f);
    }

    if (writeOut) {
        *(float4*)(out + (size_t)node * DOUT + c0)     = make_float4(o[0], o[1], o[2], o[3]);
        *(float4*)(out + (size_t)node * DOUT + c0 + 4) = make_float4(o[4], o[5], o[6], o[7]);
    } else {
        // write bf16 hi/lo fragments for next layer's A (row=node, cols c0..c0+7)
        int r16  = node >> 4;
        int ks   = c0 >> 4;
        int word = (((c0 >> 3) & 1) << 1) | ((node >> 3) & 1);
        uint32_t* AH = (uint32_t*)g_Ahi4;
        uint32_t* AL = (uint32_t*)g_Alo4;
        size_t base = ((size_t)r16 * 256 + (size_t)ks * 32) * 4;
#pragma unroll
        for (int p = 0; p < 4; p++) {
            int ln = ((node & 7) << 2) | p;
            uint32_t hw, lw;
            split2(o[2 * p], o[2 * p + 1], hw, lw);
            AH[base + ln * 4 + word] = hw;
            AL[base + ln * 4 + word] = lw;
        }
    }
}

// ---------------- launch ----------------------------------------------------
static cudaStream_t g_s2;
static cudaEvent_t  g_evFork, g_evJoin, g_evB12;
static bool g_init = false;

extern "C" void kernel_launch(void* const* d_in, const int* in_sizes, int n_in,
                              void* d_out, int out_size) {
    if (!g_init) {
        cudaStreamCreateWithFlags(&g_s2, cudaStreamNonBlocking);
        cudaEventCreateWithFlags(&g_evFork, cudaEventDisableTiming);
        cudaEventCreateWithFlags(&g_evJoin, cudaEventDisableTiming);
        cudaEventCreateWithFlags(&g_evB12, cudaEventDisableTiming);
        g_init = true;
    }

    const float* x   = (const float*)d_in[0];
    const int*   ei  = (const int*)d_in[1];   // JAX x64 disabled -> int32
    const int*   src = ei;
    const int*   dst = ei + EE;

    const float* Wl[3] = {(const float*)d_in[4],  (const float*)d_in[9],  (const float*)d_in[14]};
    const float* bl[3] = {(const float*)d_in[5],  (const float*)d_in[10], (const float*)d_in[15]};
    const float* Wr[3] = {(const float*)d_in[6],  (const float*)d_in[11], (const float*)d_in[16]};
    const float* Ws[3] = {(const float*)d_in[7],  (const float*)d_in[12], (const float*)d_in[17]};
    const float* bs[3] = {(const float*)d_in[8],  (const float*)d_in[13], (const float*)d_in[18]};

    const int TB = 256;
    const int douts[3] = {128, 128, 64};

    // ---- fork: CSR build first (gates agg0), then convB1/2 on side stream --
    cudaEventRecord(g_evFork, 0);
    cudaStreamWaitEvent(g_s2, g_evFork, 0);
    k_zero_deg<<<(NPAD + TB - 1) / TB, TB, 0, g_s2>>>();
    k_count<<<(EE + TB - 1) / TB, TB, 0, g_s2>>>(dst);
    k_scan<<<1, 1024, 0, g_s2>>>();
    k_place<<<(EE + TB - 1) / TB, TB, 0, g_s2>>>(src, dst);
    cudaEventRecord(g_evJoin, g_s2);
    for (int L = 1; L < 3; L++) {
        int bItems = (2 * douts[L] / 8) * 256;
        k_convB<<<(bItems + TB - 1) / TB, TB, 0, g_s2>>>(
            Wl[L], Wr[L], Ws[L], bl[L], bs[L], douts[L], L);
    }
    cudaEventRecord(g_evB12, g_s2);

    // ---- main chain: convB0, convA -> (mm -> agg) x3 ----
    {
        int bItems = (2 * douts[0] / 8) * 256;
        k_convB<<<(bItems + TB - 1) / TB, TB>>>(
            Wl[0], Wr[0], Ws[0], bl[0], bs[0], douts[0], 0);
    }
    k_convA<<<(NPAD * 16 + TB - 1) / TB, TB>>>(x);

    for (int L = 0; L < 3; L++) {
        int dout  = douts[L];
        int dout2 = 2 * dout;
        int last  = (L == 2);

        if (L == 1) cudaStreamWaitEvent(0, g_evB12, 0);  // B1/B2 ready

        dim3 gg(NTILES, dout2 / 128);
        k_mm<<<gg, 256>>>(dout, L);

        if (L == 0) cudaStreamWaitEvent(0, g_evJoin, 0); // CSR ready before agg0

        if (dout == 128) {
            k_agg<16, 128><<<(NN * 16 + TB - 1) / TB, TB>>>(
                (float*)d_out, last ? 1 : 0, last ? 0 : 1, L);
        } else {
            k_agg<8, 64><<<(NN * 8 + TB - 1) / TB, TB>>>(
                (float*)d_out, last ? 1 : 0, last ? 0 : 1, L);
        }
    }
}